// round 8
// baseline (speedup 1.0000x reference)
#include <cuda_runtime.h>
#include <cuda_bf16.h>
#include <cuda_fp16.h>
#include <cstdint>

#define MAX_N 100000
#define MAX_E 1600000
#define D 128
#define NB_MAX 128

// Scratch (device globals -- no allocation allowed)
__device__ __half g_hh[(size_t)MAX_N * D];     // 25.6 MB fp16 h
__device__ float g_si[MAX_N];
__device__ float g_sj[MAX_N];
__device__ int   g_cnt[MAX_N];                 // edge hist; countdown restores to 0
__device__ int   g_offp[MAX_N];                // block-local exclusive prefix
__device__ int   g_bsum[NB_MAX];
__device__ int   g_bpre[NB_MAX];
__device__ uint2 g_de[MAX_E + MAX_N];          // packed (dst, exp(score))

__device__ __forceinline__ unsigned h2_to_u32(__half2 h) {
    unsigned u; *reinterpret_cast<__half2*>(&u) = h; return u;
}
__device__ __forceinline__ __half2 u32_to_h2(unsigned u) {
    return *reinterpret_cast<__half2*>(&u);
}

// ---------------------------------------------------------------------------
// Tensor-core GEMM: h = x @ W^T + b via mma.sync m16n8k16 f16f16f32.
// Block tile 64x128 (256 thr, 8 warps = 4M x 2N, warp strip 16x64, 32 accums)
// -> ~64 regs -> 4 blocks/SM -> 50% occupancy for latency hiding.
// ---------------------------------------------------------------------------
#define GBM 64
#define KC 64
#define XPITCH 72              // smem row pitch in halves (64 + 8 pad)
#define HPITCH 136             // epilogue pitch (128 + 8 pad)

__global__ __launch_bounds__(256, 4)
void gemm_kernel(const float* __restrict__ x, const float* __restrict__ W,
                 const float* __restrict__ b, const float* __restrict__ Watt,
                 int n) {
    // xs: 64x72 halves (9216 B), ws: 128x72 halves (18432 B) -> 27648 B
    __shared__ __align__(16) char smem_raw[(GBM + 128) * XPITCH * 2];
    __half (*xs)[XPITCH] = (__half(*)[XPITCH])smem_raw;
    __half (*ws)[XPITCH] = (__half(*)[XPITCH])(smem_raw + GBM * XPITCH * 2);
    __half (*hs)[HPITCH] = (__half(*)[HPITCH])smem_raw;   // epilogue reuse (17408 B)

    int tid = threadIdx.x;
    int wid = tid >> 5;
    int lane = tid & 31;
    int gid = lane >> 2;
    int tig = lane & 3;
    int wm = wid & 3;           // 4 row groups of 16
    int wn = wid >> 2;          // 2 col groups of 64
    int row0 = blockIdx.x * GBM;

    float c[8][4];
#pragma unroll
    for (int ni = 0; ni < 8; ni++)
#pragma unroll
        for (int r = 0; r < 4; r++) c[ni][r] = 0.f;

#pragma unroll
    for (int kk = 0; kk < D; kk += KC) {
        // x tile: 64 rows x 64 cols fp32 -> fp16 (1024 float4, 4 per thread)
#pragma unroll
        for (int r = 0; r < 4; r++) {
            int idx = tid + r * 256;
            int row = idx >> 4;
            int c4 = (idx & 15) * 4;
            float4 v = make_float4(0.f, 0.f, 0.f, 0.f);
            int gr = row0 + row;
            if (gr < n) v = *(const float4*)&x[(size_t)gr * D + kk + c4];
            unsigned p0 = h2_to_u32(__floats2half2_rn(v.x, v.y));
            unsigned p1 = h2_to_u32(__floats2half2_rn(v.z, v.w));
            *(uint2*)&xs[row][c4] = make_uint2(p0, p1);
        }
        // W tile: 128 x 64 (2048 float4, 8 per thread)
#pragma unroll
        for (int r = 0; r < 8; r++) {
            int idx = tid + r * 256;
            int cc = idx >> 4;
            int c4 = (idx & 15) * 4;
            float4 v = *(const float4*)&W[(size_t)cc * D + kk + c4];
            unsigned p0 = h2_to_u32(__floats2half2_rn(v.x, v.y));
            unsigned p1 = h2_to_u32(__floats2half2_rn(v.z, v.w));
            *(uint2*)&ws[cc][c4] = make_uint2(p0, p1);
        }
        __syncthreads();

#pragma unroll
        for (int ks = 0; ks < KC / 16; ks++) {
            int kb = ks * 16 + tig * 2;
            int ra = wm * 16 + gid;
            unsigned a0 = *(const unsigned*)&xs[ra][kb];
            unsigned a1 = *(const unsigned*)&xs[ra + 8][kb];
            unsigned a2 = *(const unsigned*)&xs[ra][kb + 8];
            unsigned a3 = *(const unsigned*)&xs[ra + 8][kb + 8];
#pragma unroll
            for (int ni = 0; ni < 8; ni++) {
                int cb = wn * 64 + ni * 8 + gid;
                unsigned b0 = *(const unsigned*)&ws[cb][kb];
                unsigned b1 = *(const unsigned*)&ws[cb][kb + 8];
                asm volatile(
                    "mma.sync.aligned.m16n8k16.row.col.f32.f16.f16.f32 "
                    "{%0,%1,%2,%3}, {%4,%5,%6,%7}, {%8,%9}, {%0,%1,%2,%3};"
                    : "+f"(c[ni][0]), "+f"(c[ni][1]),
                      "+f"(c[ni][2]), "+f"(c[ni][3])
                    : "r"(a0), "r"(a1), "r"(a2), "r"(a3),
                      "r"(b0), "r"(b1));
            }
        }
        __syncthreads();
    }

    // epilogue pass 1: +bias, fp16, stage in smem
#pragma unroll
    for (int ni = 0; ni < 8; ni++) {
        int rr = wm * 16 + gid;
        int col = wn * 64 + ni * 8 + tig * 2;
        float bx = __ldg(&b[col]);
        float by = __ldg(&b[col + 1]);
        *(unsigned*)&hs[rr][col] =
            h2_to_u32(__floats2half2_rn(c[ni][0] + bx, c[ni][1] + by));
        *(unsigned*)&hs[rr + 8][col] =
            h2_to_u32(__floats2half2_rn(c[ni][2] + bx, c[ni][3] + by));
    }
    __syncthreads();

    // epilogue pass 2: coalesced store + fused s_i/s_j (4 iters of 16 rows)
    int tx = tid & 15;
    int tyr = tid >> 4;
    float ai_r[8], aj_r[8];
#pragma unroll
    for (int j = 0; j < 8; j++) {
        ai_r[j] = __ldg(&Watt[tx * 8 + j]);
        aj_r[j] = __ldg(&Watt[D + tx * 8 + j]);
    }
#pragma unroll
    for (int it = 0; it < 4; it++) {
        int row = it * 16 + tyr;
        int gr = row0 + row;
        uint4 v = *(const uint4*)&hs[row][tx * 8];
        float2 f0 = __half22float2(u32_to_h2(v.x));
        float2 f1 = __half22float2(u32_to_h2(v.y));
        float2 f2 = __half22float2(u32_to_h2(v.z));
        float2 f3 = __half22float2(u32_to_h2(v.w));
        float psi = f0.x*ai_r[0] + f0.y*ai_r[1] + f1.x*ai_r[2] + f1.y*ai_r[3]
                  + f2.x*ai_r[4] + f2.y*ai_r[5] + f3.x*ai_r[6] + f3.y*ai_r[7];
        float psj = f0.x*aj_r[0] + f0.y*aj_r[1] + f1.x*aj_r[2] + f1.y*aj_r[3]
                  + f2.x*aj_r[4] + f2.y*aj_r[5] + f3.x*aj_r[6] + f3.y*aj_r[7];
#pragma unroll
        for (int o = 8; o; o >>= 1) {
            psi += __shfl_down_sync(0xffffffffu, psi, o, 16);
            psj += __shfl_down_sync(0xffffffffu, psj, o, 16);
        }
        if (gr < n) {
            *(uint4*)&g_hh[(size_t)gr * D + tx * 8] = v;
            if (tx == 0) { g_si[gr] = psi; g_sj[gr] = psj; }
        }
    }
}

// ---------------------------------------------------------------------------
__global__ void hist_kernel(const int* __restrict__ ei, int E) {
    int t = blockIdx.x * blockDim.x + threadIdx.x;
    if (t < E) atomicAdd(&g_cnt[ei[t]], 1);
}

// ---------------------------------------------------------------------------
// scan over (cnt[i] + 1): +1 is the implicit self-loop. g_cnt stays the raw
// histogram; scatter's countdown restores it to 0 for the next graph replay.
// ---------------------------------------------------------------------------
__global__ void scan1_kernel(int n) {
    __shared__ int sh[1024];
    int i = blockIdx.x * 1024 + threadIdx.x;
    int v = (i < n) ? (g_cnt[i] + 1) : 0;
    sh[threadIdx.x] = v;
    __syncthreads();
    for (int off = 1; off < 1024; off <<= 1) {
        int t = (threadIdx.x >= off) ? sh[threadIdx.x - off] : 0;
        __syncthreads();
        sh[threadIdx.x] += t;
        __syncthreads();
    }
    if (i < n) g_offp[i] = sh[threadIdx.x] - v;
    if (threadIdx.x == 1023) g_bsum[blockIdx.x] = sh[1023];
}

__global__ void scan2_kernel(int nb) {
    __shared__ int sh[NB_MAX];
    int t = threadIdx.x;
    int v = (t < nb) ? g_bsum[t] : 0;
    sh[t] = v;
    __syncthreads();
    for (int off = 1; off < NB_MAX; off <<= 1) {
        int u = (t >= off) ? sh[t - off] : 0;
        __syncthreads();
        sh[t] += u;
        __syncthreads();
    }
    if (t < nb) g_bpre[t] = sh[t] - v;
}

// ---------------------------------------------------------------------------
// scatter: edges countdown into slots [base, base+cnt-1]; the self-loop takes
// the fixed last slot (next segment base - 1). g_cnt ends at 0 (replay-safe).
// ---------------------------------------------------------------------------
__global__ void scatter_kernel(const int* __restrict__ ei,
                               const float* __restrict__ batt, int E, int n) {
    int t = blockIdx.x * blockDim.x + threadIdx.x;
    if (t >= E + n) return;
    int src, dst, pos;
    if (t < E) {
        src = ei[t]; dst = ei[E + t];
        int old = atomicAdd(&g_cnt[src], -1);
        pos = g_offp[src] + g_bpre[src >> 10] + old - 1;
    } else {
        src = t - E; dst = src;
        int nxt = (src + 1 < n)
            ? (g_offp[src + 1] + g_bpre[(src + 1) >> 10])
            : (E + n);
        pos = nxt - 1;
    }
    float sc = g_si[src] + g_sj[dst] + batt[0];
    sc = (sc >= 0.f) ? sc : 0.01f * sc;
    float e = expf(sc);
    g_de[pos] = make_uint2((unsigned)dst, __float_as_uint(e));
}

// ---------------------------------------------------------------------------
// aggregation: warp per src node, fp16 gather, fp32 accumulate,
// fused normalize + ELU, coalesced write.
// ---------------------------------------------------------------------------
__global__ __launch_bounds__(256)
void aggregate_kernel(float* __restrict__ out, int n, int total) {
    int w = (blockIdx.x * blockDim.x + threadIdx.x) >> 5;
    int lane = threadIdx.x & 31;
    if (w >= n) return;
    int s = g_offp[w] + g_bpre[w >> 10];
    int e = (w + 1 < n) ? (g_offp[w + 1] + g_bpre[(w + 1) >> 10]) : total;

    float4 acc = make_float4(0.f, 0.f, 0.f, 0.f);
    float den = 0.f;

    int k = s;
    for (; k + 3 < e; k += 4) {
        uint2 de0 = g_de[k],     de1 = g_de[k + 1];
        uint2 de2 = g_de[k + 2], de3 = g_de[k + 3];
        uint2 r0 = *(const uint2*)&g_hh[(size_t)de0.x * D + lane * 4];
        uint2 r1 = *(const uint2*)&g_hh[(size_t)de1.x * D + lane * 4];
        uint2 r2 = *(const uint2*)&g_hh[(size_t)de2.x * D + lane * 4];
        uint2 r3 = *(const uint2*)&g_hh[(size_t)de3.x * D + lane * 4];
        float e0 = __uint_as_float(de0.y), e1 = __uint_as_float(de1.y);
        float e2 = __uint_as_float(de2.y), e3 = __uint_as_float(de3.y);
        float2 a0 = __half22float2(u32_to_h2(r0.x));
        float2 a1 = __half22float2(u32_to_h2(r0.y));
        acc.x += e0 * a0.x; acc.y += e0 * a0.y; acc.z += e0 * a1.x; acc.w += e0 * a1.y;
        a0 = __half22float2(u32_to_h2(r1.x));
        a1 = __half22float2(u32_to_h2(r1.y));
        acc.x += e1 * a0.x; acc.y += e1 * a0.y; acc.z += e1 * a1.x; acc.w += e1 * a1.y;
        a0 = __half22float2(u32_to_h2(r2.x));
        a1 = __half22float2(u32_to_h2(r2.y));
        acc.x += e2 * a0.x; acc.y += e2 * a0.y; acc.z += e2 * a1.x; acc.w += e2 * a1.y;
        a0 = __half22float2(u32_to_h2(r3.x));
        a1 = __half22float2(u32_to_h2(r3.y));
        acc.x += e3 * a0.x; acc.y += e3 * a0.y; acc.z += e3 * a1.x; acc.w += e3 * a1.y;
        den += (e0 + e1) + (e2 + e3);
    }
    for (; k < e; k++) {
        uint2 de0 = g_de[k];
        uint2 r0 = *(const uint2*)&g_hh[(size_t)de0.x * D + lane * 4];
        float e0 = __uint_as_float(de0.y);
        float2 a0 = __half22float2(u32_to_h2(r0.x));
        float2 a1 = __half22float2(u32_to_h2(r0.y));
        acc.x += e0 * a0.x; acc.y += e0 * a0.y; acc.z += e0 * a1.x; acc.w += e0 * a1.y;
        den += e0;
    }

    float inv = 1.f / den;
    float4 o;
    o.x = acc.x * inv; o.y = acc.y * inv; o.z = acc.z * inv; o.w = acc.w * inv;
    o.x = (o.x > 0.f) ? o.x : expm1f(o.x);
    o.y = (o.y > 0.f) ? o.y : expm1f(o.y);
    o.z = (o.z > 0.f) ? o.z : expm1f(o.z);
    o.w = (o.w > 0.f) ? o.w : expm1f(o.w);
    *(float4*)&out[(size_t)w * D + lane * 4] = o;
}

// ---------------------------------------------------------------------------
extern "C" void kernel_launch(void* const* d_in, const int* in_sizes, int n_in,
                              void* d_out, int out_size) {
    const float* x    = (const float*)d_in[0];
    const int*   ei   = (const int*)  d_in[1];
    const float* W    = (const float*)d_in[2];
    const float* b    = (const float*)d_in[3];
    const float* Watt = (const float*)d_in[4];
    const float* batt = (const float*)d_in[5];
    float* out = (float*)d_out;

    int n = in_sizes[0] / D;
    int E = in_sizes[1] / 2;
    int total = E + n;
    int nb = (n + 1023) / 1024;

    // side stream + events for fork/join inside graph capture (created once)
    static cudaStream_t s1 = nullptr;
    static cudaEvent_t ev_fork = nullptr, ev_join = nullptr;
    if (s1 == nullptr) {
        cudaStreamCreateWithFlags(&s1, cudaStreamNonBlocking);
        cudaEventCreateWithFlags(&ev_fork, cudaEventDisableTiming);
        cudaEventCreateWithFlags(&ev_join, cudaEventDisableTiming);
    }

    // fork: edge pipeline (hist -> scans) concurrent with GEMM
    cudaEventRecord(ev_fork, 0);
    cudaStreamWaitEvent(s1, ev_fork, 0);
    hist_kernel<<<(E + 255) / 256, 256, 0, s1>>>(ei, E);
    scan1_kernel<<<nb, 1024, 0, s1>>>(n);
    scan2_kernel<<<1, NB_MAX, 0, s1>>>(nb);
    cudaEventRecord(ev_join, s1);

    gemm_kernel<<<(n + GBM - 1) / GBM, 256>>>(x, W, b, Watt, n);

    cudaStreamWaitEvent(0, ev_join, 0);
    scatter_kernel<<<(total + 255) / 256, 256>>>(ei, batt, E, n);
    aggregate_kernel<<<((long long)n * 32 + 255) / 256, 256>>>(out, n, total);
}

// round 10
// speedup vs baseline: 1.0310x; 1.0310x over previous
#include <cuda_runtime.h>
#include <cuda_bf16.h>
#include <cuda_fp16.h>
#include <cstdint>

#define MAX_N 100000
#define MAX_E 1600000
#define D 128
#define NB_MAX 128

// Scratch (device globals -- no allocation allowed)
__device__ __half g_hh[(size_t)MAX_N * D];     // 25.6 MB fp16 h
__device__ float g_si[MAX_N];
__device__ float g_sj[MAX_N];
__device__ int   g_cnt[MAX_N];                 // edge hist; countdown restores to 0
__device__ int   g_offp[MAX_N];                // block-local exclusive prefix
__device__ int   g_bsum[NB_MAX];
__device__ int   g_bpre[NB_MAX];
__device__ uint2 g_de[MAX_E + MAX_N];          // packed (dst, exp(score))

__device__ __forceinline__ unsigned h2_to_u32(__half2 h) {
    unsigned u; *reinterpret_cast<__half2*>(&u) = h; return u;
}
__device__ __forceinline__ __half2 u32_to_h2(unsigned u) {
    return *reinterpret_cast<__half2*>(&u);
}

// L2 evict_last policy (created once per thread, cheap)
__device__ __forceinline__ uint64_t mk_policy_el() {
    uint64_t p;
    asm("createpolicy.fractional.L2::evict_last.b64 %0, 1.0;" : "=l"(p));
    return p;
}
// L2-pinned 8B load via cache_hint (for g_hh rows, reused across many edges)
__device__ __forceinline__ uint2 ld_hh8(const __half* p, uint64_t pol) {
    uint2 v;
    asm volatile("ld.global.nc.L2::cache_hint.v2.u32 {%0,%1}, [%2], %3;"
                 : "=r"(v.x), "=r"(v.y) : "l"(p), "l"(pol));
    return v;
}
// streaming 8B load (read-once g_de)
__device__ __forceinline__ uint2 ld_de8(const uint2* p) {
    uint2 v;
    asm volatile("ld.global.cs.v2.u32 {%0,%1}, [%2];"
                 : "=r"(v.x), "=r"(v.y) : "l"(p));
    return v;
}

// ---------------------------------------------------------------------------
// Tensor-core GEMM: h = x @ W^T + b via mma.sync m16n8k16 f16f16f32.
// Block tile 128x128, K chunked 2x64. 8 warps: 4 in M x 2 in N.
// (round-7 proven configuration)
// ---------------------------------------------------------------------------
#define KC 64
#define XPITCH 72              // smem row pitch in halves (64 + 8 pad)
#define HPITCH 136             // epilogue pitch (128 + 8 pad)

__global__ __launch_bounds__(256, 2)
void gemm_kernel(const float* __restrict__ x, const float* __restrict__ W,
                 const float* __restrict__ b, const float* __restrict__ Watt,
                 int n) {
    __shared__ __align__(16) char smem_raw[2 * 128 * XPITCH * 2]; // 36864 B
    __half (*xs)[XPITCH] = (__half(*)[XPITCH])smem_raw;
    __half (*ws)[XPITCH] = (__half(*)[XPITCH])(smem_raw + 128 * XPITCH * 2);
    __half (*hs)[HPITCH] = (__half(*)[HPITCH])smem_raw;   // epilogue reuse

    int tid = threadIdx.x;
    int wid = tid >> 5;
    int lane = tid & 31;
    int gid = lane >> 2;
    int tig = lane & 3;
    int wm = wid & 3;
    int wn = wid >> 2;
    int row0 = blockIdx.x * 128;

    float c[2][8][4];
#pragma unroll
    for (int mi = 0; mi < 2; mi++)
#pragma unroll
        for (int ni = 0; ni < 8; ni++)
#pragma unroll
            for (int r = 0; r < 4; r++) c[mi][ni][r] = 0.f;

#pragma unroll
    for (int kk = 0; kk < D; kk += KC) {
#pragma unroll
        for (int r = 0; r < 8; r++) {
            int idx = tid + r * 256;
            int row = idx >> 4;
            int c4 = (idx & 15) * 4;
            float4 v = make_float4(0.f, 0.f, 0.f, 0.f);
            int gr = row0 + row;
            if (gr < n) v = *(const float4*)&x[(size_t)gr * D + kk + c4];
            unsigned p0 = h2_to_u32(__floats2half2_rn(v.x, v.y));
            unsigned p1 = h2_to_u32(__floats2half2_rn(v.z, v.w));
            *(uint2*)&xs[row][c4] = make_uint2(p0, p1);
        }
#pragma unroll
        for (int r = 0; r < 8; r++) {
            int idx = tid + r * 256;
            int cc = idx >> 4;
            int c4 = (idx & 15) * 4;
            float4 v = *(const float4*)&W[(size_t)cc * D + kk + c4];
            unsigned p0 = h2_to_u32(__floats2half2_rn(v.x, v.y));
            unsigned p1 = h2_to_u32(__floats2half2_rn(v.z, v.w));
            *(uint2*)&ws[cc][c4] = make_uint2(p0, p1);
        }
        __syncthreads();

#pragma unroll
        for (int ks = 0; ks < KC / 16; ks++) {
            int kb = ks * 16 + tig * 2;
            unsigned a[2][4];
#pragma unroll
            for (int mi = 0; mi < 2; mi++) {
                int ra = wm * 32 + mi * 16 + gid;
                a[mi][0] = *(const unsigned*)&xs[ra][kb];
                a[mi][1] = *(const unsigned*)&xs[ra + 8][kb];
                a[mi][2] = *(const unsigned*)&xs[ra][kb + 8];
                a[mi][3] = *(const unsigned*)&xs[ra + 8][kb + 8];
            }
#pragma unroll
            for (int ni = 0; ni < 8; ni++) {
                int cb = wn * 64 + ni * 8 + gid;
                unsigned b0 = *(const unsigned*)&ws[cb][kb];
                unsigned b1 = *(const unsigned*)&ws[cb][kb + 8];
#pragma unroll
                for (int mi = 0; mi < 2; mi++) {
                    asm volatile(
                        "mma.sync.aligned.m16n8k16.row.col.f32.f16.f16.f32 "
                        "{%0,%1,%2,%3}, {%4,%5,%6,%7}, {%8,%9}, {%0,%1,%2,%3};"
                        : "+f"(c[mi][ni][0]), "+f"(c[mi][ni][1]),
                          "+f"(c[mi][ni][2]), "+f"(c[mi][ni][3])
                        : "r"(a[mi][0]), "r"(a[mi][1]), "r"(a[mi][2]), "r"(a[mi][3]),
                          "r"(b0), "r"(b1));
                }
            }
        }
        __syncthreads();
    }

    // epilogue pass 1: +bias, fp16, stage in smem
#pragma unroll
    for (int mi = 0; mi < 2; mi++) {
#pragma unroll
        for (int ni = 0; ni < 8; ni++) {
            int rr = wm * 32 + mi * 16 + gid;
            int col = wn * 64 + ni * 8 + tig * 2;
            float bx = __ldg(&b[col]);
            float by = __ldg(&b[col + 1]);
            *(unsigned*)&hs[rr][col] =
                h2_to_u32(__floats2half2_rn(c[mi][ni][0] + bx, c[mi][ni][1] + by));
            *(unsigned*)&hs[rr + 8][col] =
                h2_to_u32(__floats2half2_rn(c[mi][ni][2] + bx, c[mi][ni][3] + by));
        }
    }
    __syncthreads();

    // epilogue pass 2: coalesced store + fused s_i/s_j
    int tx = tid & 15;
    int tyr = tid >> 4;
    float ai_r[8], aj_r[8];
#pragma unroll
    for (int j = 0; j < 8; j++) {
        ai_r[j] = __ldg(&Watt[tx * 8 + j]);
        aj_r[j] = __ldg(&Watt[D + tx * 8 + j]);
    }
#pragma unroll
    for (int it = 0; it < 8; it++) {
        int row = it * 16 + tyr;
        int gr = row0 + row;
        uint4 v = *(const uint4*)&hs[row][tx * 8];
        float2 f0 = __half22float2(u32_to_h2(v.x));
        float2 f1 = __half22float2(u32_to_h2(v.y));
        float2 f2 = __half22float2(u32_to_h2(v.z));
        float2 f3 = __half22float2(u32_to_h2(v.w));
        float psi = f0.x*ai_r[0] + f0.y*ai_r[1] + f1.x*ai_r[2] + f1.y*ai_r[3]
                  + f2.x*ai_r[4] + f2.y*ai_r[5] + f3.x*ai_r[6] + f3.y*ai_r[7];
        float psj = f0.x*aj_r[0] + f0.y*aj_r[1] + f1.x*aj_r[2] + f1.y*aj_r[3]
                  + f2.x*aj_r[4] + f2.y*aj_r[5] + f3.x*aj_r[6] + f3.y*aj_r[7];
#pragma unroll
        for (int o = 8; o; o >>= 1) {
            psi += __shfl_down_sync(0xffffffffu, psi, o, 16);
            psj += __shfl_down_sync(0xffffffffu, psj, o, 16);
        }
        if (gr < n) {
            *(uint4*)&g_hh[(size_t)gr * D + tx * 8] = v;
            if (tx == 0) { g_si[gr] = psi; g_sj[gr] = psj; }
        }
    }
}

// ---------------------------------------------------------------------------
__global__ void hist_kernel(const int* __restrict__ ei, int E) {
    int t = blockIdx.x * blockDim.x + threadIdx.x;
    if (t < E) atomicAdd(&g_cnt[ei[t]], 1);
}

// ---------------------------------------------------------------------------
// scan over (cnt[i] + 1): +1 is the implicit self-loop. g_cnt stays the raw
// histogram; scatter's countdown restores it to 0 for the next graph replay.
// ---------------------------------------------------------------------------
__global__ void scan1_kernel(int n) {
    __shared__ int sh[1024];
    int i = blockIdx.x * 1024 + threadIdx.x;
    int v = (i < n) ? (g_cnt[i] + 1) : 0;
    sh[threadIdx.x] = v;
    __syncthreads();
    for (int off = 1; off < 1024; off <<= 1) {
        int t = (threadIdx.x >= off) ? sh[threadIdx.x - off] : 0;
        __syncthreads();
        sh[threadIdx.x] += t;
        __syncthreads();
    }
    if (i < n) g_offp[i] = sh[threadIdx.x] - v;
    if (threadIdx.x == 1023) g_bsum[blockIdx.x] = sh[1023];
}

__global__ void scan2_kernel(int nb) {
    __shared__ int sh[NB_MAX];
    int t = threadIdx.x;
    int v = (t < nb) ? g_bsum[t] : 0;
    sh[t] = v;
    __syncthreads();
    for (int off = 1; off < NB_MAX; off <<= 1) {
        int u = (t >= off) ? sh[t - off] : 0;
        __syncthreads();
        sh[t] += u;
        __syncthreads();
    }
    if (t < nb) g_bpre[t] = sh[t] - v;
}

// ---------------------------------------------------------------------------
// scatter: edges countdown into slots [base, base+cnt-1]; the self-loop takes
// the fixed last slot (next segment base - 1). g_cnt ends at 0 (replay-safe).
// ---------------------------------------------------------------------------
__global__ void scatter_kernel(const int* __restrict__ ei,
                               const float* __restrict__ batt, int E, int n) {
    int t = blockIdx.x * blockDim.x + threadIdx.x;
    if (t >= E + n) return;
    int src, dst, pos;
    if (t < E) {
        src = ei[t]; dst = ei[E + t];
        int old = atomicAdd(&g_cnt[src], -1);
        pos = g_offp[src] + g_bpre[src >> 10] + old - 1;
    } else {
        src = t - E; dst = src;
        int nxt = (src + 1 < n)
            ? (g_offp[src + 1] + g_bpre[(src + 1) >> 10])
            : (E + n);
        pos = nxt - 1;
    }
    float sc = g_si[src] + g_sj[dst] + batt[0];
    sc = (sc >= 0.f) ? sc : 0.01f * sc;
    float e = expf(sc);
    g_de[pos] = make_uint2((unsigned)dst, __float_as_uint(e));
}

// ---------------------------------------------------------------------------
// aggregation: warp per src node. g_hh gathers pinned in L2 (evict_last via
// cache_hint policy), g_de streamed (read-once), out written streaming
// (st.cs). fp32 accumulate, fused normalize + ELU.
// ---------------------------------------------------------------------------
__global__ __launch_bounds__(256)
void aggregate_kernel(float* __restrict__ out, int n, int total) {
    int w = (blockIdx.x * blockDim.x + threadIdx.x) >> 5;
    int lane = threadIdx.x & 31;
    if (w >= n) return;
    uint64_t pol = mk_policy_el();
    int s = g_offp[w] + g_bpre[w >> 10];
    int e = (w + 1 < n) ? (g_offp[w + 1] + g_bpre[(w + 1) >> 10]) : total;

    float4 acc = make_float4(0.f, 0.f, 0.f, 0.f);
    float den = 0.f;

    int k = s;
    for (; k + 3 < e; k += 4) {
        uint2 de0 = ld_de8(&g_de[k]);
        uint2 de1 = ld_de8(&g_de[k + 1]);
        uint2 de2 = ld_de8(&g_de[k + 2]);
        uint2 de3 = ld_de8(&g_de[k + 3]);
        uint2 r0 = ld_hh8(&g_hh[(size_t)de0.x * D + lane * 4], pol);
        uint2 r1 = ld_hh8(&g_hh[(size_t)de1.x * D + lane * 4], pol);
        uint2 r2 = ld_hh8(&g_hh[(size_t)de2.x * D + lane * 4], pol);
        uint2 r3 = ld_hh8(&g_hh[(size_t)de3.x * D + lane * 4], pol);
        float e0 = __uint_as_float(de0.y), e1 = __uint_as_float(de1.y);
        float e2 = __uint_as_float(de2.y), e3 = __uint_as_float(de3.y);
        float2 a0 = __half22float2(u32_to_h2(r0.x));
        float2 a1 = __half22float2(u32_to_h2(r0.y));
        acc.x += e0 * a0.x; acc.y += e0 * a0.y; acc.z += e0 * a1.x; acc.w += e0 * a1.y;
        a0 = __half22float2(u32_to_h2(r1.x));
        a1 = __half22float2(u32_to_h2(r1.y));
        acc.x += e1 * a0.x; acc.y += e1 * a0.y; acc.z += e1 * a1.x; acc.w += e1 * a1.y;
        a0 = __half22float2(u32_to_h2(r2.x));
        a1 = __half22float2(u32_to_h2(r2.y));
        acc.x += e2 * a0.x; acc.y += e2 * a0.y; acc.z += e2 * a1.x; acc.w += e2 * a1.y;
        a0 = __half22float2(u32_to_h2(r3.x));
        a1 = __half22float2(u32_to_h2(r3.y));
        acc.x += e3 * a0.x; acc.y += e3 * a0.y; acc.z += e3 * a1.x; acc.w += e3 * a1.y;
        den += (e0 + e1) + (e2 + e3);
    }
    for (; k < e; k++) {
        uint2 de0 = ld_de8(&g_de[k]);
        uint2 r0 = ld_hh8(&g_hh[(size_t)de0.x * D + lane * 4], pol);
        float e0 = __uint_as_float(de0.y);
        float2 a0 = __half22float2(u32_to_h2(r0.x));
        float2 a1 = __half22float2(u32_to_h2(r0.y));
        acc.x += e0 * a0.x; acc.y += e0 * a0.y; acc.z += e0 * a1.x; acc.w += e0 * a1.y;
        den += e0;
    }

    float inv = 1.f / den;
    float4 o;
    o.x = acc.x * inv; o.y = acc.y * inv; o.z = acc.z * inv; o.w = acc.w * inv;
    o.x = (o.x > 0.f) ? o.x : expm1f(o.x);
    o.y = (o.y > 0.f) ? o.y : expm1f(o.y);
    o.z = (o.z > 0.f) ? o.z : expm1f(o.z);
    o.w = (o.w > 0.f) ? o.w : expm1f(o.w);
    // streaming store: out is write-once, never re-read -> keep it out of L2
    float* p = &out[(size_t)w * D + lane * 4];
    asm volatile("st.global.cs.v4.f32 [%0], {%1,%2,%3,%4};"
                 :: "l"(p), "f"(o.x), "f"(o.y), "f"(o.z), "f"(o.w) : "memory");
}

// ---------------------------------------------------------------------------
extern "C" void kernel_launch(void* const* d_in, const int* in_sizes, int n_in,
                              void* d_out, int out_size) {
    const float* x    = (const float*)d_in[0];
    const int*   ei   = (const int*)  d_in[1];
    const float* W    = (const float*)d_in[2];
    const float* b    = (const float*)d_in[3];
    const float* Watt = (const float*)d_in[4];
    const float* batt = (const float*)d_in[5];
    float* out = (float*)d_out;

    int n = in_sizes[0] / D;
    int E = in_sizes[1] / 2;
    int total = E + n;
    int nb = (n + 1023) / 1024;

    // side stream + events for fork/join inside graph capture (created once)
    static cudaStream_t s1 = nullptr;
    static cudaEvent_t ev_fork = nullptr, ev_join = nullptr;
    if (s1 == nullptr) {
        cudaStreamCreateWithFlags(&s1, cudaStreamNonBlocking);
        cudaEventCreateWithFlags(&ev_fork, cudaEventDisableTiming);
        cudaEventCreateWithFlags(&ev_join, cudaEventDisableTiming);
    }

    // fork: edge pipeline (hist -> scans) concurrent with GEMM
    cudaEventRecord(ev_fork, 0);
    cudaStreamWaitEvent(s1, ev_fork, 0);
    hist_kernel<<<(E + 255) / 256, 256, 0, s1>>>(ei, E);
    scan1_kernel<<<nb, 1024, 0, s1>>>(n);
    scan2_kernel<<<1, NB_MAX, 0, s1>>>(nb);
    cudaEventRecord(ev_join, s1);

    gemm_kernel<<<(n + 127) / 128, 256>>>(x, W, b, Watt, n);

    cudaStreamWaitEvent(0, ev_join, 0);
    scatter_kernel<<<(total + 255) / 256, 256>>>(ei, batt, E, n);
    aggregate_kernel<<<((long long)n * 32 + 255) / 256, 256>>>(out, n, total);
}

// round 11
// speedup vs baseline: 1.0495x; 1.0180x over previous
#include <cuda_runtime.h>
#include <cuda_bf16.h>
#include <cuda_fp16.h>
#include <cstdint>

#define MAX_N 100000
#define MAX_E 1600000
#define D 128
#define NB_MAX 128

// Scratch (device globals -- no allocation allowed)
__device__ __half g_hh[(size_t)MAX_N * D];     // 25.6 MB fp16 h
__device__ float g_si[MAX_N];
__device__ float g_sj[MAX_N];
__device__ int   g_cnt[MAX_N];                 // edge hist; countdown restores to 0
__device__ int   g_offp[MAX_N];                // block-local exclusive prefix
__device__ int   g_bsum[NB_MAX];
__device__ int   g_bpre[NB_MAX];
__device__ int   g_d[MAX_E];                   // dst sorted by src (edges only)

__device__ __forceinline__ unsigned h2_to_u32(__half2 h) {
    unsigned u; *reinterpret_cast<__half2*>(&u) = h; return u;
}
__device__ __forceinline__ __half2 u32_to_h2(unsigned u) {
    return *reinterpret_cast<__half2*>(&u);
}

// ---------------------------------------------------------------------------
// Tensor-core GEMM: h = x @ W^T + b via mma.sync m16n8k16 f16f16f32.
// Block tile 128x128, K chunked 2x64. 8 warps: 4 in M x 2 in N.
// (round-7 proven configuration)
// ---------------------------------------------------------------------------
#define KC 64
#define XPITCH 72              // smem row pitch in halves (64 + 8 pad)
#define HPITCH 136             // epilogue pitch (128 + 8 pad)

__global__ __launch_bounds__(256, 2)
void gemm_kernel(const float* __restrict__ x, const float* __restrict__ W,
                 const float* __restrict__ b, const float* __restrict__ Watt,
                 int n) {
    __shared__ __align__(16) char smem_raw[2 * 128 * XPITCH * 2]; // 36864 B
    __half (*xs)[XPITCH] = (__half(*)[XPITCH])smem_raw;
    __half (*ws)[XPITCH] = (__half(*)[XPITCH])(smem_raw + 128 * XPITCH * 2);
    __half (*hs)[HPITCH] = (__half(*)[HPITCH])smem_raw;   // epilogue reuse

    int tid = threadIdx.x;
    int wid = tid >> 5;
    int lane = tid & 31;
    int gid = lane >> 2;
    int tig = lane & 3;
    int wm = wid & 3;
    int wn = wid >> 2;
    int row0 = blockIdx.x * 128;

    float c[2][8][4];
#pragma unroll
    for (int mi = 0; mi < 2; mi++)
#pragma unroll
        for (int ni = 0; ni < 8; ni++)
#pragma unroll
            for (int r = 0; r < 4; r++) c[mi][ni][r] = 0.f;

#pragma unroll
    for (int kk = 0; kk < D; kk += KC) {
#pragma unroll
        for (int r = 0; r < 8; r++) {
            int idx = tid + r * 256;
            int row = idx >> 4;
            int c4 = (idx & 15) * 4;
            float4 v = make_float4(0.f, 0.f, 0.f, 0.f);
            int gr = row0 + row;
            if (gr < n) v = *(const float4*)&x[(size_t)gr * D + kk + c4];
            unsigned p0 = h2_to_u32(__floats2half2_rn(v.x, v.y));
            unsigned p1 = h2_to_u32(__floats2half2_rn(v.z, v.w));
            *(uint2*)&xs[row][c4] = make_uint2(p0, p1);
        }
#pragma unroll
        for (int r = 0; r < 8; r++) {
            int idx = tid + r * 256;
            int cc = idx >> 4;
            int c4 = (idx & 15) * 4;
            float4 v = *(const float4*)&W[(size_t)cc * D + kk + c4];
            unsigned p0 = h2_to_u32(__floats2half2_rn(v.x, v.y));
            unsigned p1 = h2_to_u32(__floats2half2_rn(v.z, v.w));
            *(uint2*)&ws[cc][c4] = make_uint2(p0, p1);
        }
        __syncthreads();

#pragma unroll
        for (int ks = 0; ks < KC / 16; ks++) {
            int kb = ks * 16 + tig * 2;
            unsigned a[2][4];
#pragma unroll
            for (int mi = 0; mi < 2; mi++) {
                int ra = wm * 32 + mi * 16 + gid;
                a[mi][0] = *(const unsigned*)&xs[ra][kb];
                a[mi][1] = *(const unsigned*)&xs[ra + 8][kb];
                a[mi][2] = *(const unsigned*)&xs[ra][kb + 8];
                a[mi][3] = *(const unsigned*)&xs[ra + 8][kb + 8];
            }
#pragma unroll
            for (int ni = 0; ni < 8; ni++) {
                int cb = wn * 64 + ni * 8 + gid;
                unsigned b0 = *(const unsigned*)&ws[cb][kb];
                unsigned b1 = *(const unsigned*)&ws[cb][kb + 8];
#pragma unroll
                for (int mi = 0; mi < 2; mi++) {
                    asm volatile(
                        "mma.sync.aligned.m16n8k16.row.col.f32.f16.f16.f32 "
                        "{%0,%1,%2,%3}, {%4,%5,%6,%7}, {%8,%9}, {%0,%1,%2,%3};"
                        : "+f"(c[mi][ni][0]), "+f"(c[mi][ni][1]),
                          "+f"(c[mi][ni][2]), "+f"(c[mi][ni][3])
                        : "r"(a[mi][0]), "r"(a[mi][1]), "r"(a[mi][2]), "r"(a[mi][3]),
                          "r"(b0), "r"(b1));
                }
            }
        }
        __syncthreads();
    }

    // epilogue pass 1: +bias, fp16, stage in smem
#pragma unroll
    for (int mi = 0; mi < 2; mi++) {
#pragma unroll
        for (int ni = 0; ni < 8; ni++) {
            int rr = wm * 32 + mi * 16 + gid;
            int col = wn * 64 + ni * 8 + tig * 2;
            float bx = __ldg(&b[col]);
            float by = __ldg(&b[col + 1]);
            *(unsigned*)&hs[rr][col] =
                h2_to_u32(__floats2half2_rn(c[mi][ni][0] + bx, c[mi][ni][1] + by));
            *(unsigned*)&hs[rr + 8][col] =
                h2_to_u32(__floats2half2_rn(c[mi][ni][2] + bx, c[mi][ni][3] + by));
        }
    }
    __syncthreads();

    // epilogue pass 2: coalesced store + fused s_i/s_j
    int tx = tid & 15;
    int tyr = tid >> 4;
    float ai_r[8], aj_r[8];
#pragma unroll
    for (int j = 0; j < 8; j++) {
        ai_r[j] = __ldg(&Watt[tx * 8 + j]);
        aj_r[j] = __ldg(&Watt[D + tx * 8 + j]);
    }
#pragma unroll
    for (int it = 0; it < 8; it++) {
        int row = it * 16 + tyr;
        int gr = row0 + row;
        uint4 v = *(const uint4*)&hs[row][tx * 8];
        float2 f0 = __half22float2(u32_to_h2(v.x));
        float2 f1 = __half22float2(u32_to_h2(v.y));
        float2 f2 = __half22float2(u32_to_h2(v.z));
        float2 f3 = __half22float2(u32_to_h2(v.w));
        float psi = f0.x*ai_r[0] + f0.y*ai_r[1] + f1.x*ai_r[2] + f1.y*ai_r[3]
                  + f2.x*ai_r[4] + f2.y*ai_r[5] + f3.x*ai_r[6] + f3.y*ai_r[7];
        float psj = f0.x*aj_r[0] + f0.y*aj_r[1] + f1.x*aj_r[2] + f1.y*aj_r[3]
                  + f2.x*aj_r[4] + f2.y*aj_r[5] + f3.x*aj_r[6] + f3.y*aj_r[7];
#pragma unroll
        for (int o = 8; o; o >>= 1) {
            psi += __shfl_down_sync(0xffffffffu, psi, o, 16);
            psj += __shfl_down_sync(0xffffffffu, psj, o, 16);
        }
        if (gr < n) {
            *(uint4*)&g_hh[(size_t)gr * D + tx * 8] = v;
            if (tx == 0) { g_si[gr] = psi; g_sj[gr] = psj; }
        }
    }
}

// ---------------------------------------------------------------------------
__global__ void hist_kernel(const int* __restrict__ ei, int E) {
    int t = blockIdx.x * blockDim.x + threadIdx.x;
    if (t < E) atomicAdd(&g_cnt[ei[t]], 1);
}

// ---------------------------------------------------------------------------
// exclusive scan over edge counts (self-loops NOT included in slots)
// ---------------------------------------------------------------------------
__global__ void scan1_kernel(int n) {
    __shared__ int sh[1024];
    int i = blockIdx.x * 1024 + threadIdx.x;
    int v = (i < n) ? g_cnt[i] : 0;
    sh[threadIdx.x] = v;
    __syncthreads();
    for (int off = 1; off < 1024; off <<= 1) {
        int t = (threadIdx.x >= off) ? sh[threadIdx.x - off] : 0;
        __syncthreads();
        sh[threadIdx.x] += t;
        __syncthreads();
    }
    if (i < n) g_offp[i] = sh[threadIdx.x] - v;
    if (threadIdx.x == 1023) g_bsum[blockIdx.x] = sh[1023];
}

__global__ void scan2_kernel(int nb) {
    __shared__ int sh[NB_MAX];
    int t = threadIdx.x;
    int v = (t < nb) ? g_bsum[t] : 0;
    sh[t] = v;
    __syncthreads();
    for (int off = 1; off < NB_MAX; off <<= 1) {
        int u = (t >= off) ? sh[t - off] : 0;
        __syncthreads();
        sh[t] += u;
        __syncthreads();
    }
    if (t < nb) g_bpre[t] = sh[t] - v;
}

// ---------------------------------------------------------------------------
// sort: pure counting-sort scatter of dst by src (score-free -> runs
// concurrently with the GEMM). g_cnt counts down to 0 (replay-safe).
// ---------------------------------------------------------------------------
__global__ void sort_kernel(const int* __restrict__ ei, int E) {
    int t = blockIdx.x * blockDim.x + threadIdx.x;
    if (t >= E) return;
    int src = ei[t];
    int dst = ei[E + t];
    int old = atomicAdd(&g_cnt[src], -1);
    g_d[g_offp[src] + g_bpre[src >> 10] + old - 1] = dst;
}

// ---------------------------------------------------------------------------
// aggregation: warp per src node. Scores computed inline:
// phase 1 (lane-parallel, 32 edges/chunk): e_k = exp(lrelu(si[w]+sj[d_k]+b));
// phase 2: broadcast (d, e) via shuffle, gather h rows, accumulate.
// Self-loop handled analytically (no slot). Fused normalize + ELU.
// ---------------------------------------------------------------------------
__global__ __launch_bounds__(256)
void aggregate_kernel(float* __restrict__ out, const float* __restrict__ batt,
                      int n, int E) {
    int w = (blockIdx.x * blockDim.x + threadIdx.x) >> 5;
    int lane = threadIdx.x & 31;
    if (w >= n) return;
    int s = g_offp[w] + g_bpre[w >> 10];
    int e = (w + 1 < n) ? (g_offp[w + 1] + g_bpre[(w + 1) >> 10]) : E;

    float bb = __ldg(batt);
    float si_w = g_si[w];

    // self loop: e_self * h[w]
    float scs = si_w + g_sj[w] + bb;
    scs = (scs >= 0.f) ? scs : 0.01f * scs;
    float es = expf(scs);

    float4 acc;
    {
        uint2 rw = *(const uint2*)&g_hh[(size_t)w * D + lane * 4];
        float2 a0 = __half22float2(u32_to_h2(rw.x));
        float2 a1 = __half22float2(u32_to_h2(rw.y));
        acc = make_float4(es * a0.x, es * a0.y, es * a1.x, es * a1.y);
    }
    float denp = 0.f;   // per-lane partial (edges only)

    for (int cs = s; cs < e; cs += 32) {
        int m = e - cs; if (m > 32) m = 32;
        int dk = 0; float ek = 0.f;
        if (lane < m) {
            dk = g_d[cs + lane];
            float sc = si_w + __ldg(&g_sj[dk]) + bb;
            sc = (sc >= 0.f) ? sc : 0.01f * sc;
            ek = expf(sc);
        }
        denp += ek;
        int j = 0;
        for (; j + 3 < m; j += 4) {
            int d0 = __shfl_sync(0xffffffffu, dk, j);
            int d1 = __shfl_sync(0xffffffffu, dk, j + 1);
            int d2 = __shfl_sync(0xffffffffu, dk, j + 2);
            int d3 = __shfl_sync(0xffffffffu, dk, j + 3);
            float e0 = __shfl_sync(0xffffffffu, ek, j);
            float e1 = __shfl_sync(0xffffffffu, ek, j + 1);
            float e2 = __shfl_sync(0xffffffffu, ek, j + 2);
            float e3 = __shfl_sync(0xffffffffu, ek, j + 3);
            uint2 r0 = *(const uint2*)&g_hh[(size_t)d0 * D + lane * 4];
            uint2 r1 = *(const uint2*)&g_hh[(size_t)d1 * D + lane * 4];
            uint2 r2 = *(const uint2*)&g_hh[(size_t)d2 * D + lane * 4];
            uint2 r3 = *(const uint2*)&g_hh[(size_t)d3 * D + lane * 4];
            float2 a0 = __half22float2(u32_to_h2(r0.x));
            float2 a1 = __half22float2(u32_to_h2(r0.y));
            acc.x += e0 * a0.x; acc.y += e0 * a0.y; acc.z += e0 * a1.x; acc.w += e0 * a1.y;
            a0 = __half22float2(u32_to_h2(r1.x));
            a1 = __half22float2(u32_to_h2(r1.y));
            acc.x += e1 * a0.x; acc.y += e1 * a0.y; acc.z += e1 * a1.x; acc.w += e1 * a1.y;
            a0 = __half22float2(u32_to_h2(r2.x));
            a1 = __half22float2(u32_to_h2(r2.y));
            acc.x += e2 * a0.x; acc.y += e2 * a0.y; acc.z += e2 * a1.x; acc.w += e2 * a1.y;
            a0 = __half22float2(u32_to_h2(r3.x));
            a1 = __half22float2(u32_to_h2(r3.y));
            acc.x += e3 * a0.x; acc.y += e3 * a0.y; acc.z += e3 * a1.x; acc.w += e3 * a1.y;
        }
        for (; j < m; j++) {
            int d0 = __shfl_sync(0xffffffffu, dk, j);
            float e0 = __shfl_sync(0xffffffffu, ek, j);
            uint2 r0 = *(const uint2*)&g_hh[(size_t)d0 * D + lane * 4];
            float2 a0 = __half22float2(u32_to_h2(r0.x));
            float2 a1 = __half22float2(u32_to_h2(r0.y));
            acc.x += e0 * a0.x; acc.y += e0 * a0.y; acc.z += e0 * a1.x; acc.w += e0 * a1.y;
        }
    }

    // reduce den across lanes, add self-loop term
    float den = denp;
#pragma unroll
    for (int o = 16; o; o >>= 1) den += __shfl_xor_sync(0xffffffffu, den, o);
    den += es;

    float inv = 1.f / den;
    float4 o;
    o.x = acc.x * inv; o.y = acc.y * inv; o.z = acc.z * inv; o.w = acc.w * inv;
    o.x = (o.x > 0.f) ? o.x : expm1f(o.x);
    o.y = (o.y > 0.f) ? o.y : expm1f(o.y);
    o.z = (o.z > 0.f) ? o.z : expm1f(o.z);
    o.w = (o.w > 0.f) ? o.w : expm1f(o.w);
    float* p = &out[(size_t)w * D + lane * 4];
    asm volatile("st.global.cs.v4.f32 [%0], {%1,%2,%3,%4};"
                 :: "l"(p), "f"(o.x), "f"(o.y), "f"(o.z), "f"(o.w) : "memory");
}

// ---------------------------------------------------------------------------
extern "C" void kernel_launch(void* const* d_in, const int* in_sizes, int n_in,
                              void* d_out, int out_size) {
    const float* x    = (const float*)d_in[0];
    const int*   ei   = (const int*)  d_in[1];
    const float* W    = (const float*)d_in[2];
    const float* b    = (const float*)d_in[3];
    const float* Watt = (const float*)d_in[4];
    const float* batt = (const float*)d_in[5];
    float* out = (float*)d_out;

    int n = in_sizes[0] / D;
    int E = in_sizes[1] / 2;
    int nb = (n + 1023) / 1024;

    // side stream + events for fork/join inside graph capture (created once)
    static cudaStream_t s1 = nullptr;
    static cudaEvent_t ev_fork = nullptr, ev_join = nullptr;
    if (s1 == nullptr) {
        cudaStreamCreateWithFlags(&s1, cudaStreamNonBlocking);
        cudaEventCreateWithFlags(&ev_fork, cudaEventDisableTiming);
        cudaEventCreateWithFlags(&ev_join, cudaEventDisableTiming);
    }

    // fork: FULL edge pipeline (hist -> scans -> sort) concurrent with GEMM
    cudaEventRecord(ev_fork, 0);
    cudaStreamWaitEvent(s1, ev_fork, 0);
    hist_kernel<<<(E + 255) / 256, 256, 0, s1>>>(ei, E);
    scan1_kernel<<<nb, 1024, 0, s1>>>(n);
    scan2_kernel<<<1, NB_MAX, 0, s1>>>(nb);
    sort_kernel<<<(E + 255) / 256, 256, 0, s1>>>(ei, E);
    cudaEventRecord(ev_join, s1);

    gemm_kernel<<<(n + 127) / 128, 256>>>(x, W, b, Watt, n);

    cudaStreamWaitEvent(0, ev_join, 0);
    aggregate_kernel<<<((long long)n * 32 + 255) / 256, 256>>>(out, batt, n, E);
}